// round 14
// baseline (speedup 1.0000x reference)
#include <cuda_runtime.h>
#include <cuda_fp16.h>
#include <mma.h>
#include <math.h>

using namespace nvcuda;

#define NN 50000
#define NE 800000
#define NHEADS 4
#define SLOPE 0.2f
#define XLD 304              // padded fp16 row stride for x (608B, 16B-aligned)
#define N1B 408              // B1 columns: 400 (W1) + 8 (Wl1 score cols); 816B rows, 16B-aligned

// ---------------- scratch (static device globals; no allocation) ----------------
__device__ __half g_projh1[NN * 400];      // 40 MB
__device__ __half g_projh2[NN * 512];      // 51.2 MB
__device__ __half g_xh[NN * XLD];          // 30.4 MB (pad cols stay 0)
__device__ __half g_b1h[300 * N1B];        // W1 fp16 with Wl1 appended as cols 400..407
__device__ __half g_w2h[400 * 512];
__device__ __half g_h1h[NN * 400];         // 40 MB
__device__ float  g_wl2[400 * 8];          // fp32 for aggregate1-fused scores2
__device__ float  g_el1[NN * NHEADS];
__device__ float  g_er1[NN * NHEADS];
__device__ float  g_el2[NN * NHEADS];
__device__ float  g_er2[NN * NHEADS];
__device__ float  g_alpha[NE * 4];
__device__ float  g_inv[NN * 4];
__device__ int    g_deg[NN];
__device__ int    g_rowptr[NN + 1];
__device__ int    g_cursor[NN];
__device__ int    g_srcs[NE];

__device__ __forceinline__ float lrelu(float x) { return x > 0.f ? x : SLOPE * x; }

// ---------------- FUSED setup ----------------
#define N_XPAD (NN * 75)
#define N_W1Q  (300 * 100)     // quads of W1 into strided b1h
#define N_W2Q  (400 * 128)
#define N_WL1  (300 * 8)
#define N_WL2  (400 * 8)
#define SETUP_TOTAL (N_XPAD + N_W1Q + N_W2Q + N_WL1 + N_WL2 + NE)

__device__ __forceinline__ float wl_dot(const float* W, const float* al, const float* ar,
                                        int idx, int DH) {
    int k = idx >> 3, j = idx & 7;
    const float* av = (j < 4) ? (al + j * DH) : (ar + (j - 4) * DH);
    const float* wrow = W + (size_t)k * (4 * DH) + (j & 3) * DH;
    float s = 0.f;
    for (int d = 0; d < DH; d++) s = fmaf(wrow[d], av[d], s);
    return s;
}

__global__ void setup_kernel(const float* __restrict__ x,
                             const float* __restrict__ W1, const float* __restrict__ al1, const float* __restrict__ ar1,
                             const float* __restrict__ W2, const float* __restrict__ al2, const float* __restrict__ ar2,
                             const int* __restrict__ dst) {
    int i = blockIdx.x * blockDim.x + threadIdx.x;
    if (i < N_XPAD) {
        int row = i / 75, q = i % 75;
        float4 v = *reinterpret_cast<const float4*>(x + (size_t)row * 300 + q * 4);
        __half* o = g_xh + (size_t)row * XLD + q * 4;
        reinterpret_cast<__half2*>(o)[0] = __floats2half2_rn(v.x, v.y);
        reinterpret_cast<__half2*>(o)[1] = __floats2half2_rn(v.z, v.w);
        return;
    }
    i -= N_XPAD;
    if (i < N_W1Q) {                        // W1 -> b1h cols 0..399 (row stride N1B)
        int row = i / 100, q = i % 100;
        float4 v = reinterpret_cast<const float4*>(W1)[i];
        __half* o = g_b1h + (size_t)row * N1B + q * 4;
        reinterpret_cast<__half2*>(o)[0] = __floats2half2_rn(v.x, v.y);
        reinterpret_cast<__half2*>(o)[1] = __floats2half2_rn(v.z, v.w);
        return;
    }
    i -= N_W1Q;
    if (i < N_W2Q) {
        float4 v = reinterpret_cast<const float4*>(W2)[i];
        reinterpret_cast<__half2*>(g_w2h)[2 * i]     = __floats2half2_rn(v.x, v.y);
        reinterpret_cast<__half2*>(g_w2h)[2 * i + 1] = __floats2half2_rn(v.z, v.w);
        return;
    }
    i -= N_W2Q;
    if (i < N_WL1) {                        // Wl1 -> b1h cols 400..407 (fp16)
        float s = wl_dot(W1, al1, ar1, i, 100);
        g_b1h[(size_t)(i >> 3) * N1B + 400 + (i & 7)] = __float2half_rn(s);
        return;
    }
    i -= N_WL1;
    if (i < N_WL2) { g_wl2[i] = wl_dot(W2, al2, ar2, i, 128); return; }
    i -= N_WL2;
    if (i < NE) atomicAdd(&g_deg[dst[i]], 1);
}

// ---------------- cp.async helpers ----------------
__device__ __forceinline__ void cp_async16(void* smem, const void* g) {
    unsigned saddr = (unsigned)__cvta_generic_to_shared(smem);
    asm volatile("cp.async.cg.shared.global [%0], [%1], 16;\n" :: "r"(saddr), "l"(g));
}
__device__ __forceinline__ void cp_commit() { asm volatile("cp.async.commit_group;\n" ::: "memory"); }
__device__ __forceinline__ void cp_wait0()  { asm volatile("cp.async.wait_group 0;\n" ::: "memory"); }
__device__ __forceinline__ void cp_wait1()  { asm volatile("cp.async.wait_group 1;\n" ::: "memory"); }

// ---------------- FP16 WMMA GEMM (fp32 acc), 3-stage cp.async ----------------
// SC: B has 8 score columns at [Nout, Nout+8) -> route to el/er (fp32).
#define GBM 128
#define GBK 32
#define LDA 40

template <int GBN, bool SC>
__global__ void __launch_bounds__(256, 2)
gemm_f16(const __half* __restrict__ A, const __half* __restrict__ B,
         __half* __restrict__ Ch, float* __restrict__ el, float* __restrict__ er,
         int M, int Nout, int NB, int K, int lda) {
    constexpr int WNF = GBN / 64;
    constexpr int WNT = 16 * WNF;
    constexpr int LDB = GBN + 8;
    constexpr int LDC = GBN + 4;
    constexpr int ABUF = GBM * LDA;
    constexpr int BBUF = GBK * LDB;
    constexpr int TILEBUF = ABUF + BBUF;

    extern __shared__ __align__(16) char smem_raw[];
    __half* sbuf = reinterpret_cast<__half*>(smem_raw);

    const int tid  = threadIdx.x;
    const int warp = tid >> 5;
    const int wm   = warp & 1;
    const int wn   = warp >> 1;
    const int bm   = blockIdx.y * GBM;
    const int bn   = blockIdx.x * GBN;

    wmma::fragment<wmma::accumulator, 16, 16, 16, float> acc[4][WNF];
#pragma unroll
    for (int i = 0; i < 4; i++)
#pragma unroll
        for (int j = 0; j < WNF; j++) wmma::fill_fragment(acc[i][j], 0.f);

    auto load_tile = [&](int buf, int kt) {
        __half* As = sbuf + buf * TILEBUF;
        __half* Bs = As + ABUF;
#pragma unroll
        for (int it = 0; it < 2; it++) {
            int s = tid + 256 * it;
            int r = s >> 2, c8 = s & 3;
            int gr = bm + r, gc = kt + c8 * 8;
            __half* dstp = &As[r * LDA + c8 * 8];
            if (gr < M && gc < K) cp_async16(dstp, A + (size_t)gr * lda + gc);
            else *reinterpret_cast<float4*>(dstp) = make_float4(0.f, 0.f, 0.f, 0.f);
        }
        constexpr int BCH = GBK * GBN / 8;
#pragma unroll
        for (int s = 0; s < BCH; s += 256) {
            int sl = s + tid;
            int r = sl / (GBN / 8), c8 = sl % (GBN / 8);
            int gr = kt + r, gc = bn + c8 * 8;
            __half* dstp = &Bs[r * LDB + c8 * 8];
            if (gr < K && gc < NB) cp_async16(dstp, B + (size_t)gr * NB + gc);
            else *reinterpret_cast<float4*>(dstp) = make_float4(0.f, 0.f, 0.f, 0.f);
        }
        cp_commit();
    };

    load_tile(0, 0);
    if (GBK < K) load_tile(1, GBK);

    int buf = 0;
    for (int kt = 0; kt < K; kt += GBK) {
        if (kt + GBK < K) cp_wait1(); else cp_wait0();
        __syncthreads();
        if (kt + 2 * GBK < K) load_tile((buf + 2) % 3, kt + 2 * GBK);

        const __half* As = sbuf + buf * TILEBUF;
        const __half* Bs = As + ABUF;
#pragma unroll
        for (int ks = 0; ks < GBK; ks += 16) {
            wmma::fragment<wmma::matrix_a, 16, 16, 16, __half, wmma::row_major> af[4];
            wmma::fragment<wmma::matrix_b, 16, 16, 16, __half, wmma::row_major> bf[WNF];
#pragma unroll
            for (int i = 0; i < 4; i++)
                wmma::load_matrix_sync(af[i], &As[(wm * 64 + i * 16) * LDA + ks], LDA);
#pragma unroll
            for (int j = 0; j < WNF; j++)
                wmma::load_matrix_sync(bf[j], &Bs[ks * LDB + wn * WNT + j * 16], LDB);
#pragma unroll
            for (int i = 0; i < 4; i++)
#pragma unroll
                for (int j = 0; j < WNF; j++)
                    wmma::mma_sync(acc[i][j], af[i], bf[j], acc[i][j]);
        }
        buf = (buf + 1) % 3;
        __syncthreads();
    }

    // ---- epilogue: two 64-row halves; fp16 out + optional score-column routing ----
    float* CS = reinterpret_cast<float*>(smem_raw);
#pragma unroll
    for (int half = 0; half < 2; half++) {
        if (wm == half) {
#pragma unroll
            for (int i = 0; i < 4; i++)
#pragma unroll
                for (int j = 0; j < WNF; j++)
                    wmma::store_matrix_sync(&CS[(i * 16) * LDC + wn * WNT + j * 16],
                                            acc[i][j], LDC, wmma::mem_row_major);
        }
        __syncthreads();
        constexpr int OS = 16 * GBN;
#pragma unroll
        for (int s = 0; s < OS; s += 256) {
            int sl = s + tid;
            int r = sl / (GBN / 4), c4 = sl % (GBN / 4);
            int gr = bm + half * 64 + r, gc = bn + c4 * 4;
            if (gr < M) {
                if (gc < Nout) {
                    float4 v = *reinterpret_cast<float4*>(&CS[r * LDC + c4 * 4]);
                    *reinterpret_cast<__half2*>(Ch + (size_t)gr * Nout + gc)     = __floats2half2_rn(v.x, v.y);
                    *reinterpret_cast<__half2*>(Ch + (size_t)gr * Nout + gc + 2) = __floats2half2_rn(v.z, v.w);
                } else if (SC) {
                    if (gc == Nout)
                        reinterpret_cast<float4*>(el)[gr] = *reinterpret_cast<float4*>(&CS[r * LDC + c4 * 4]);
                    else if (gc == Nout + 4)
                        reinterpret_cast<float4*>(er)[gr] = *reinterpret_cast<float4*>(&CS[r * LDC + c4 * 4]);
                }
            }
        }
        __syncthreads();
    }
}

// ---------------- CSR scan + scatter ----------------
__global__ void scan_kernel() {
    __shared__ int sh[1024];
    const int t = threadIdx.x;
    const int CHUNK = (NN + 1023) / 1024;
    int beg = t * CHUNK;
    int end = min(beg + CHUNK, NN);
    int s = 0;
    for (int i = beg; i < end; i++) s += g_deg[i];
    sh[t] = s;
    __syncthreads();
    for (int off = 1; off < 1024; off <<= 1) {
        int v = (t >= off) ? sh[t - off] : 0;
        __syncthreads();
        sh[t] += v;
        __syncthreads();
    }
    int run = t ? sh[t - 1] : 0;
    for (int i = beg; i < end; i++) {
        g_rowptr[i] = run;
        g_cursor[i] = run;
        run += g_deg[i];
    }
    if (t == 0) g_rowptr[NN] = sh[1023];
}

__global__ void scatter_kernel(const int* __restrict__ src, const int* __restrict__ dst) {
    int e = blockIdx.x * blockDim.x + threadIdx.x;
    if (e < NE) {
        int p = atomicAdd(&g_cursor[dst[e]], 1);
        g_srcs[p] = src[e];
    }
}

// ---------------- per-dst softmax weights: one warp per dst node ----------------
__global__ void alpha_kernel(const float* __restrict__ el, const float* __restrict__ er,
                             float* __restrict__ alpha, float* __restrict__ invp) {
    const int d = blockIdx.x * 8 + (threadIdx.x >> 5);
    if (d >= NN) return;
    const int lane = threadIdx.x & 31;
    const int beg = g_rowptr[d];
    const int end = g_rowptr[d + 1];

    const float4 erd = reinterpret_cast<const float4*>(er)[d];

    float4 m = make_float4(-1e30f, -1e30f, -1e30f, -1e30f);
    for (int e = beg + lane; e < end; e += 32) {
        int sn = g_srcs[e];
        float4 l = reinterpret_cast<const float4*>(el)[sn];
        float4 v;
        v.x = lrelu(l.x + erd.x);
        v.y = lrelu(l.y + erd.y);
        v.z = lrelu(l.z + erd.z);
        v.w = lrelu(l.w + erd.w);
        reinterpret_cast<float4*>(alpha)[e] = v;
        m.x = fmaxf(m.x, v.x); m.y = fmaxf(m.y, v.y);
        m.z = fmaxf(m.z, v.z); m.w = fmaxf(m.w, v.w);
    }
#pragma unroll
    for (int o = 16; o; o >>= 1) {
        m.x = fmaxf(m.x, __shfl_xor_sync(0xffffffffu, m.x, o));
        m.y = fmaxf(m.y, __shfl_xor_sync(0xffffffffu, m.y, o));
        m.z = fmaxf(m.z, __shfl_xor_sync(0xffffffffu, m.z, o));
        m.w = fmaxf(m.w, __shfl_xor_sync(0xffffffffu, m.w, o));
    }

    float4 s = make_float4(0.f, 0.f, 0.f, 0.f);
    for (int e = beg + lane; e < end; e += 32) {
        float4 v = reinterpret_cast<float4*>(alpha)[e];
        v.x = __expf(v.x - m.x); v.y = __expf(v.y - m.y);
        v.z = __expf(v.z - m.z); v.w = __expf(v.w - m.w);
        reinterpret_cast<float4*>(alpha)[e] = v;
        s.x += v.x; s.y += v.y; s.z += v.z; s.w += v.w;
    }
#pragma unroll
    for (int o = 16; o; o >>= 1) {
        s.x += __shfl_xor_sync(0xffffffffu, s.x, o);
        s.y += __shfl_xor_sync(0xffffffffu, s.y, o);
        s.z += __shfl_xor_sync(0xffffffffu, s.z, o);
        s.w += __shfl_xor_sync(0xffffffffu, s.w, o);
    }
    if (lane == 0) {
        float4 inv;
        inv.x = 1.f / (s.x + 1e-9f); inv.y = 1.f / (s.y + 1e-9f);
        inv.z = 1.f / (s.z + 1e-9f); inv.w = 1.f / (s.w + 1e-9f);
        reinterpret_cast<float4*>(invp)[d] = inv;
    }
}

// ---------------- aggregation; optional fused scores2 (SC2) ----------------
template <int DH, bool ACT, bool OUT_HALF, bool SC2>
__global__ void aggregate_kernel(const __half* __restrict__ projh,
                                 const float* __restrict__ alpha,
                                 const float* __restrict__ invp,
                                 const float* __restrict__ bias, void* __restrict__ outp,
                                 const float* __restrict__ wl2,
                                 float* __restrict__ el2, float* __restrict__ er2) {
    const int d = blockIdx.x;
    const int t = threadIdx.x;
    const bool active = t < DH;
    const int beg = g_rowptr[d];
    const int end = g_rowptr[d + 1];

    float4 acc = make_float4(0.f, 0.f, 0.f, 0.f);
    if (active) {
        const int head = (4 * t) / DH;
        const float4 invv = reinterpret_cast<const float4*>(invp)[d];
        const float inv = (head == 0) ? invv.x : (head == 1) ? invv.y : (head == 2) ? invv.z : invv.w;

#pragma unroll 2
        for (int e = beg; e < end; e++) {
            int sn = g_srcs[e];
            float4 a = reinterpret_cast<const float4*>(alpha)[e];   // broadcast
            float w = (head == 0) ? a.x : (head == 1) ? a.y : (head == 2) ? a.z : a.w;
            const __half2* ph =
                reinterpret_cast<const __half2*>(projh + (size_t)sn * (4 * DH)) + 2 * t;
            float2 p0 = __half22float2(ph[0]);
            float2 p1 = __half22float2(ph[1]);
            acc.x = fmaf(w, p0.x, acc.x);
            acc.y = fmaf(w, p0.y, acc.y);
            acc.z = fmaf(w, p1.x, acc.z);
            acc.w = fmaf(w, p1.y, acc.w);
        }
        float4 b = reinterpret_cast<const float4*>(bias)[t];
        acc.x = fmaf(acc.x, inv, b.x);
        acc.y = fmaf(acc.y, inv, b.y);
        acc.z = fmaf(acc.z, inv, b.z);
        acc.w = fmaf(acc.w, inv, b.w);
        if (ACT) {
            acc.x = lrelu(acc.x); acc.y = lrelu(acc.y);
            acc.z = lrelu(acc.z); acc.w = lrelu(acc.w);
        }
        if (OUT_HALF) {
            __half2* o = reinterpret_cast<__half2*>((__half*)outp + (size_t)d * (4 * DH)) + 2 * t;
            o[0] = __floats2half2_rn(acc.x, acc.y);
            o[1] = __floats2half2_rn(acc.z, acc.w);
        } else {
            reinterpret_cast<float4*>((float*)outp)[(size_t)d * DH + t] = acc;
        }
    }

    if (SC2) {
        // scores2: part[j] = sum_k h1[d,k] * wl2[k][j]; this thread holds k = 4t..4t+3
        float part[8] = {0.f, 0.f, 0.f, 0.f, 0.f, 0.f, 0.f, 0.f};
        if (active) {
#pragma unroll
            for (int r = 0; r < 4; r++) {
                float hv = (&acc.x)[r];
                const float4* w = reinterpret_cast<const float4*>(wl2 + (size_t)(4 * t + r) * 8);
                float4 w0 = w[0], w1 = w[1];
                part[0] = fmaf(hv, w0.x, part[0]); part[1] = fmaf(hv, w0.y, part[1]);
                part[2] = fmaf(hv, w0.z, part[2]); part[3] = fmaf(hv, w0.w, part[3]);
                part[4] = fmaf(hv, w1.x, part[4]); part[5] = fmaf(hv, w1.y, part[5]);
                part[6] = fmaf(hv, w1.z, part[6]); part[7] = fmaf(hv, w1.w, part[7]);
            }
        }
#pragma unroll
        for (int j = 0; j < 8; j++)
#pragma unroll
            for (int o = 16; o; o >>= 1)
                part[j] += __shfl_xor_sync(0xffffffffu, part[j], o);
        __shared__ float red[4][8];
        const int warp = t >> 5, lane = t & 31;
        if (lane == 0)
#pragma unroll
            for (int j = 0; j < 8; j++) red[warp][j] = part[j];
        __syncthreads();
        if (t < 8) {
            float s = red[0][t] + red[1][t] + red[2][t] + red[3][t];
            if (t < 4) el2[(size_t)d * 4 + t] = s;
            else       er2[(size_t)d * 4 + (t - 4)] = s;
        }
    }
}

// ---------------- launch ----------------
extern "C" void kernel_launch(void* const* d_in, const int* in_sizes, int n_in,
                              void* d_out, int out_size) {
    const float* x   = (const float*)d_in[0];
    const float* W1  = (const float*)d_in[1];
    const float* al1 = (const float*)d_in[2];
    const float* ar1 = (const float*)d_in[3];
    const float* b1  = (const float*)d_in[4];
    const float* W2  = (const float*)d_in[5];
    const float* al2 = (const float*)d_in[6];
    const float* ar2 = (const float*)d_in[7];
    const float* b2  = (const float*)d_in[8];
    const int*   src = (const int*)d_in[9];
    const int*   dst = (const int*)d_in[10];
    float* out = (float*)d_out;

    float *el1, *er1, *el2, *er2, *alpha, *invp, *degp, *wl2;
    __half *projh1, *projh2, *xh, *b1h, *w2h, *h1h;
    cudaGetSymbolAddress((void**)&projh1, g_projh1);
    cudaGetSymbolAddress((void**)&projh2, g_projh2);
    cudaGetSymbolAddress((void**)&xh, g_xh);
    cudaGetSymbolAddress((void**)&b1h, g_b1h);
    cudaGetSymbolAddress((void**)&w2h, g_w2h);
    cudaGetSymbolAddress((void**)&h1h, g_h1h);
    cudaGetSymbolAddress((void**)&wl2, g_wl2);
    cudaGetSymbolAddress((void**)&el1, g_el1);
    cudaGetSymbolAddress((void**)&er1, g_er1);
    cudaGetSymbolAddress((void**)&el2, g_el2);
    cudaGetSymbolAddress((void**)&er2, g_er2);
    cudaGetSymbolAddress((void**)&alpha, g_alpha);
    cudaGetSymbolAddress((void**)&invp, g_inv);
    cudaGetSymbolAddress((void**)&degp, g_deg);

    constexpr int SMEM64  = 3 * (GBM * LDA + GBK * (64 + 8)) * 2;    // 44544
    constexpr int SMEM128 = 3 * (GBM * LDA + GBK * (128 + 8)) * 2;   // 56832
    cudaFuncSetAttribute(gemm_f16<64, true>,   cudaFuncAttributeMaxDynamicSharedMemorySize, SMEM64);
    cudaFuncSetAttribute(gemm_f16<128, false>, cudaFuncAttributeMaxDynamicSharedMemorySize, SMEM128);

    cudaMemsetAsync(degp, 0, NN * sizeof(int));
    setup_kernel<<<(SETUP_TOTAL + 255) / 256, 256>>>(x, W1, al1, ar1, W2, al2, ar2, dst);
    scan_kernel<<<1, 1024>>>();
    scatter_kernel<<<(NE + 255) / 256, 256>>>(src, dst);

    const int ABLK = (NN + 7) / 8;
    const int GR = (NN + GBM - 1) / GBM;

    // layer 1: GEMM with appended score columns (N1B=408; grid still 7 x-tiles)
    {
        dim3 grid((N1B + 63) / 64, GR);
        gemm_f16<64, true><<<grid, 256, SMEM64>>>(xh, b1h, projh1, el1, er1,
                                                  NN, 400, N1B, 300, XLD);
    }
    alpha_kernel<<<ABLK, 256>>>(el1, er1, alpha, invp);
    aggregate_kernel<100, true, true, true><<<NN, 128>>>(projh1, alpha, invp, b1, h1h,
                                                         wl2, el2, er2);

    // layer 2
    {
        dim3 grid(512 / 128, GR);
        gemm_f16<128, false><<<grid, 256, SMEM128>>>(h1h, w2h, projh2, nullptr, nullptr,
                                                     NN, 512, 512, 400, 400);
    }
    alpha_kernel<<<ABLK, 256>>>(el2, er2, alpha, invp);
    aggregate_kernel<128, false, false, false><<<NN, 128>>>(projh2, alpha, invp, b2, out,
                                                            nullptr, nullptr, nullptr);
}

// round 17
// speedup vs baseline: 1.7991x; 1.7991x over previous
#include <cuda_runtime.h>
#include <cuda_fp16.h>
#include <mma.h>
#include <math.h>

using namespace nvcuda;

#define NN 50000
#define NE 800000
#define NHEADS 4
#define SLOPE 0.2f
#define XLD 304              // padded fp16 row stride for x (608B, 16B-aligned)
#define N1B 408              // B1 columns: 400 (W1) + 8 (Wl1 score cols)

// ---------------- scratch (static device globals; no allocation) ----------------
__device__ __half g_projh1[NN * 400];      // 40 MB
__device__ __half g_projh2[NN * 512];      // 51.2 MB
__device__ __half g_xh[NN * XLD];          // 30.4 MB (pad cols stay 0)
__device__ __half g_b1h[300 * N1B];        // W1 fp16 with Wl1 appended as cols 400..407
__device__ __half g_w2h[400 * 512];
__device__ __half g_h1h[NN * 400];         // 40 MB
__device__ float  g_wl2[400 * 8];
__device__ float  g_el1[NN * NHEADS];
__device__ float  g_er1[NN * NHEADS];
__device__ float  g_el2[NN * NHEADS];
__device__ float  g_er2[NN * NHEADS];
__device__ float  g_alpha[NE * 4];
__device__ float  g_inv[NN * 4];
__device__ int    g_deg[NN];
__device__ int    g_rowptr[NN + 1];
__device__ int    g_cursor[NN];
__device__ int    g_srcs[NE];

__device__ __forceinline__ float lrelu(float x) { return x > 0.f ? x : SLOPE * x; }

// ---------------- FUSED setup ----------------
#define N_XPAD (NN * 75)
#define N_W1Q  (300 * 100)
#define N_W2Q  (400 * 128)
#define N_WL1  (300 * 8)
#define N_WL2  (400 * 8)
#define SETUP_TOTAL (N_XPAD + N_W1Q + N_W2Q + N_WL1 + N_WL2 + NE)

__device__ __forceinline__ float wl_dot(const float* W, const float* al, const float* ar,
                                        int idx, int DH) {
    int k = idx >> 3, j = idx & 7;
    const float* av = (j < 4) ? (al + j * DH) : (ar + (j - 4) * DH);
    const float* wrow = W + (size_t)k * (4 * DH) + (j & 3) * DH;
    float s = 0.f;
    for (int d = 0; d < DH; d++) s = fmaf(wrow[d], av[d], s);
    return s;
}

__global__ void setup_kernel(const float* __restrict__ x,
                             const float* __restrict__ W1, const float* __restrict__ al1, const float* __restrict__ ar1,
                             const float* __restrict__ W2, const float* __restrict__ al2, const float* __restrict__ ar2,
                             const int* __restrict__ dst) {
    int i = blockIdx.x * blockDim.x + threadIdx.x;
    if (i < N_XPAD) {
        int row = i / 75, q = i % 75;
        float4 v = *reinterpret_cast<const float4*>(x + (size_t)row * 300 + q * 4);
        __half* o = g_xh + (size_t)row * XLD + q * 4;
        reinterpret_cast<__half2*>(o)[0] = __floats2half2_rn(v.x, v.y);
        reinterpret_cast<__half2*>(o)[1] = __floats2half2_rn(v.z, v.w);
        return;
    }
    i -= N_XPAD;
    if (i < N_W1Q) {                        // W1 -> b1h cols 0..399 (row stride N1B)
        int row = i / 100, q = i % 100;
        float4 v = reinterpret_cast<const float4*>(W1)[i];
        __half* o = g_b1h + (size_t)row * N1B + q * 4;
        reinterpret_cast<__half2*>(o)[0] = __floats2half2_rn(v.x, v.y);
        reinterpret_cast<__half2*>(o)[1] = __floats2half2_rn(v.z, v.w);
        return;
    }
    i -= N_W1Q;
    if (i < N_W2Q) {
        float4 v = reinterpret_cast<const float4*>(W2)[i];
        reinterpret_cast<__half2*>(g_w2h)[2 * i]     = __floats2half2_rn(v.x, v.y);
        reinterpret_cast<__half2*>(g_w2h)[2 * i + 1] = __floats2half2_rn(v.z, v.w);
        return;
    }
    i -= N_W2Q;
    if (i < N_WL1) {                        // Wl1 -> b1h cols 400..407 (fp16)
        float s = wl_dot(W1, al1, ar1, i, 100);
        g_b1h[(size_t)(i >> 3) * N1B + 400 + (i & 7)] = __float2half_rn(s);
        return;
    }
    i -= N_WL1;
    if (i < N_WL2) { g_wl2[i] = wl_dot(W2, al2, ar2, i, 128); return; }
    i -= N_WL2;
    if (i < NE) atomicAdd(&g_deg[dst[i]], 1);
}

// ---------------- scores2 (standalone, h1h fp16 input) ----------------
template <int K, typename T>
__global__ void scores_w_kernel(const T* __restrict__ X, int ldx,
                                const float* __restrict__ Wl,
                                float* __restrict__ el, float* __restrict__ er) {
    __shared__ float sw[K][9];
    const int tid = threadIdx.x;
    for (int i = tid; i < K * 8; i += 256) sw[i >> 3][i & 7] = Wl[i];
    __syncthreads();
    const int warp = tid >> 5, lane = tid & 31;
    const int n = blockIdx.x * 8 + warp;
    if (n >= NN) return;
    const T* xrow = X + (size_t)n * ldx;
    float a[8] = {0.f, 0.f, 0.f, 0.f, 0.f, 0.f, 0.f, 0.f};
    for (int k = lane; k < K; k += 32) {
        float xv = (float)xrow[k];
#pragma unroll
        for (int j = 0; j < 8; j++) a[j] = fmaf(xv, sw[k][j], a[j]);
    }
#pragma unroll
    for (int j = 0; j < 8; j++)
#pragma unroll
        for (int o = 16; o; o >>= 1) a[j] += __shfl_xor_sync(0xffffffffu, a[j], o);
    if (lane == 0) {
        reinterpret_cast<float4*>(el)[n] = make_float4(a[0], a[1], a[2], a[3]);
        reinterpret_cast<float4*>(er)[n] = make_float4(a[4], a[5], a[6], a[7]);
    }
}

// ---------------- cp.async helpers ----------------
__device__ __forceinline__ void cp_async16(void* smem, const void* g) {
    unsigned saddr = (unsigned)__cvta_generic_to_shared(smem);
    asm volatile("cp.async.cg.shared.global [%0], [%1], 16;\n" :: "r"(saddr), "l"(g));
}
__device__ __forceinline__ void cp_commit() { asm volatile("cp.async.commit_group;\n" ::: "memory"); }
__device__ __forceinline__ void cp_wait0()  { asm volatile("cp.async.wait_group 0;\n" ::: "memory"); }
__device__ __forceinline__ void cp_wait1()  { asm volatile("cp.async.wait_group 1;\n" ::: "memory"); }

// ---------------- FP16 WMMA GEMM (fp32 acc), 3-stage cp.async ----------------
// SC: B has 8 score columns at [Nout, Nout+8) -> route to el/er (fp32).
#define GBM 128
#define GBK 32
#define LDA 40

template <int GBN, bool SC>
__global__ void __launch_bounds__(256, 2)
gemm_f16(const __half* __restrict__ A, const __half* __restrict__ B,
         __half* __restrict__ Ch, float* __restrict__ el, float* __restrict__ er,
         int M, int Nout, int NB, int K, int lda) {
    constexpr int WNF = GBN / 64;
    constexpr int WNT = 16 * WNF;
    constexpr int LDB = GBN + 8;
    constexpr int LDC = GBN + 4;
    constexpr int ABUF = GBM * LDA;
    constexpr int BBUF = GBK * LDB;
    constexpr int TILEBUF = ABUF + BBUF;

    extern __shared__ __align__(16) char smem_raw[];
    __half* sbuf = reinterpret_cast<__half*>(smem_raw);

    const int tid  = threadIdx.x;
    const int warp = tid >> 5;
    const int wm   = warp & 1;
    const int wn   = warp >> 1;
    const int bm   = blockIdx.y * GBM;
    const int bn   = blockIdx.x * GBN;

    wmma::fragment<wmma::accumulator, 16, 16, 16, float> acc[4][WNF];
#pragma unroll
    for (int i = 0; i < 4; i++)
#pragma unroll
        for (int j = 0; j < WNF; j++) wmma::fill_fragment(acc[i][j], 0.f);

    auto load_tile = [&](int buf, int kt) {
        __half* As = sbuf + buf * TILEBUF;
        __half* Bs = As + ABUF;
#pragma unroll
        for (int it = 0; it < 2; it++) {
            int s = tid + 256 * it;
            int r = s >> 2, c8 = s & 3;
            int gr = bm + r, gc = kt + c8 * 8;
            __half* dstp = &As[r * LDA + c8 * 8];
            if (gr < M && gc < K) cp_async16(dstp, A + (size_t)gr * lda + gc);
            else *reinterpret_cast<float4*>(dstp) = make_float4(0.f, 0.f, 0.f, 0.f);
        }
        constexpr int BCH = GBK * GBN / 8;
#pragma unroll
        for (int s = 0; s < BCH; s += 256) {
            int sl = s + tid;
            int r = sl / (GBN / 8), c8 = sl % (GBN / 8);
            int gr = kt + r, gc = bn + c8 * 8;
            __half* dstp = &Bs[r * LDB + c8 * 8];
            if (gr < K && gc < NB) cp_async16(dstp, B + (size_t)gr * NB + gc);
            else *reinterpret_cast<float4*>(dstp) = make_float4(0.f, 0.f, 0.f, 0.f);
        }
        cp_commit();
    };

    load_tile(0, 0);
    if (GBK < K) load_tile(1, GBK);

    int buf = 0;
    for (int kt = 0; kt < K; kt += GBK) {
        if (kt + GBK < K) cp_wait1(); else cp_wait0();
        __syncthreads();
        if (kt + 2 * GBK < K) load_tile((buf + 2) % 3, kt + 2 * GBK);

        const __half* As = sbuf + buf * TILEBUF;
        const __half* Bs = As + ABUF;
#pragma unroll
        for (int ks = 0; ks < GBK; ks += 16) {
            wmma::fragment<wmma::matrix_a, 16, 16, 16, __half, wmma::row_major> af[4];
            wmma::fragment<wmma::matrix_b, 16, 16, 16, __half, wmma::row_major> bf[WNF];
#pragma unroll
            for (int i = 0; i < 4; i++)
                wmma::load_matrix_sync(af[i], &As[(wm * 64 + i * 16) * LDA + ks], LDA);
#pragma unroll
            for (int j = 0; j < WNF; j++)
                wmma::load_matrix_sync(bf[j], &Bs[ks * LDB + wn * WNT + j * 16], LDB);
#pragma unroll
            for (int i = 0; i < 4; i++)
#pragma unroll
                for (int j = 0; j < WNF; j++)
                    wmma::mma_sync(acc[i][j], af[i], bf[j], acc[i][j]);
        }
        buf = (buf + 1) % 3;
        __syncthreads();
    }

    // ---- epilogue: two 64-row halves; fp16 out + optional score-column routing ----
    float* CS = reinterpret_cast<float*>(smem_raw);
#pragma unroll
    for (int half = 0; half < 2; half++) {
        if (wm == half) {
#pragma unroll
            for (int i = 0; i < 4; i++)
#pragma unroll
                for (int j = 0; j < WNF; j++)
                    wmma::store_matrix_sync(&CS[(i * 16) * LDC + wn * WNT + j * 16],
                                            acc[i][j], LDC, wmma::mem_row_major);
        }
        __syncthreads();
        constexpr int OS = 16 * GBN;
#pragma unroll
        for (int s = 0; s < OS; s += 256) {
            int sl = s + tid;
            int r = sl / (GBN / 4), c4 = sl % (GBN / 4);
            int gr = bm + half * 64 + r, gc = bn + c4 * 4;
            if (gr < M) {
                if (gc < Nout) {
                    float4 v = *reinterpret_cast<float4*>(&CS[r * LDC + c4 * 4]);
                    *reinterpret_cast<__half2*>(Ch + (size_t)gr * Nout + gc)     = __floats2half2_rn(v.x, v.y);
                    *reinterpret_cast<__half2*>(Ch + (size_t)gr * Nout + gc + 2) = __floats2half2_rn(v.z, v.w);
                } else if (SC) {
                    if (gc == Nout)
                        reinterpret_cast<float4*>(el)[gr] = *reinterpret_cast<float4*>(&CS[r * LDC + c4 * 4]);
                    else if (gc == Nout + 4)
                        reinterpret_cast<float4*>(er)[gr] = *reinterpret_cast<float4*>(&CS[r * LDC + c4 * 4]);
                }
            }
        }
        __syncthreads();
    }
}

// ---------------- CSR scan + scatter ----------------
__global__ void scan_kernel() {
    __shared__ int sh[1024];
    const int t = threadIdx.x;
    const int CHUNK = (NN + 1023) / 1024;
    int beg = t * CHUNK;
    int end = min(beg + CHUNK, NN);
    int s = 0;
    for (int i = beg; i < end; i++) s += g_deg[i];
    sh[t] = s;
    __syncthreads();
    for (int off = 1; off < 1024; off <<= 1) {
        int v = (t >= off) ? sh[t - off] : 0;
        __syncthreads();
        sh[t] += v;
        __syncthreads();
    }
    int run = t ? sh[t - 1] : 0;
    for (int i = beg; i < end; i++) {
        g_rowptr[i] = run;
        g_cursor[i] = run;
        run += g_deg[i];
    }
    if (t == 0) g_rowptr[NN] = sh[1023];
}

__global__ void scatter_kernel(const int* __restrict__ src, const int* __restrict__ dst) {
    int e = blockIdx.x * blockDim.x + threadIdx.x;
    if (e < NE) {
        int p = atomicAdd(&g_cursor[dst[e]], 1);
        g_srcs[p] = src[e];
    }
}

// ---------------- per-dst softmax weights: one warp per dst node ----------------
__global__ void alpha_kernel(const float* __restrict__ el, const float* __restrict__ er,
                             float* __restrict__ alpha, float* __restrict__ invp) {
    const int d = blockIdx.x * 8 + (threadIdx.x >> 5);
    if (d >= NN) return;
    const int lane = threadIdx.x & 31;
    const int beg = g_rowptr[d];
    const int end = g_rowptr[d + 1];

    const float4 erd = reinterpret_cast<const float4*>(er)[d];

    float4 m = make_float4(-1e30f, -1e30f, -1e30f, -1e30f);
    for (int e = beg + lane; e < end; e += 32) {
        int sn = g_srcs[e];
        float4 l = reinterpret_cast<const float4*>(el)[sn];
        float4 v;
        v.x = lrelu(l.x + erd.x);
        v.y = lrelu(l.y + erd.y);
        v.z = lrelu(l.z + erd.z);
        v.w = lrelu(l.w + erd.w);
        reinterpret_cast<float4*>(alpha)[e] = v;
        m.x = fmaxf(m.x, v.x); m.y = fmaxf(m.y, v.y);
        m.z = fmaxf(m.z, v.z); m.w = fmaxf(m.w, v.w);
    }
#pragma unroll
    for (int o = 16; o; o >>= 1) {
        m.x = fmaxf(m.x, __shfl_xor_sync(0xffffffffu, m.x, o));
        m.y = fmaxf(m.y, __shfl_xor_sync(0xffffffffu, m.y, o));
        m.z = fmaxf(m.z, __shfl_xor_sync(0xffffffffu, m.z, o));
        m.w = fmaxf(m.w, __shfl_xor_sync(0xffffffffu, m.w, o));
    }

    float4 s = make_float4(0.f, 0.f, 0.f, 0.f);
    for (int e = beg + lane; e < end; e += 32) {
        float4 v = reinterpret_cast<float4*>(alpha)[e];
        v.x = __expf(v.x - m.x); v.y = __expf(v.y - m.y);
        v.z = __expf(v.z - m.z); v.w = __expf(v.w - m.w);
        reinterpret_cast<float4*>(alpha)[e] = v;
        s.x += v.x; s.y += v.y; s.z += v.z; s.w += v.w;
    }
#pragma unroll
    for (int o = 16; o; o >>= 1) {
        s.x += __shfl_xor_sync(0xffffffffu, s.x, o);
        s.y += __shfl_xor_sync(0xffffffffu, s.y, o);
        s.z += __shfl_xor_sync(0xffffffffu, s.z, o);
        s.w += __shfl_xor_sync(0xffffffffu, s.w, o);
    }
    if (lane == 0) {
        float4 inv;
        inv.x = 1.f / (s.x + 1e-9f); inv.y = 1.f / (s.y + 1e-9f);
        inv.z = 1.f / (s.z + 1e-9f); inv.w = 1.f / (s.w + 1e-9f);
        reinterpret_cast<float4*>(invp)[d] = inv;
    }
}

// ---------------- lean aggregation (R13 form): fp16 gather, early-return ----------------
template <int DH, bool ACT, bool OUT_HALF>
__global__ void aggregate_kernel(const __half* __restrict__ projh,
                                 const float* __restrict__ alpha,
                                 const float* __restrict__ invp,
                                 const float* __restrict__ bias, void* __restrict__ outp) {
    constexpr int C4 = DH;
    const int d = blockIdx.x;
    const int t = threadIdx.x;
    const int beg = g_rowptr[d];
    const int end = g_rowptr[d + 1];
    if (t >= C4) return;

    const int head = (4 * t) / DH;
    const float4 invv = reinterpret_cast<const float4*>(invp)[d];
    const float inv = (head == 0) ? invv.x : (head == 1) ? invv.y : (head == 2) ? invv.z : invv.w;

    float4 acc = make_float4(0.f, 0.f, 0.f, 0.f);
#pragma unroll 2
    for (int e = beg; e < end; e++) {
        int sn = g_srcs[e];
        float4 a = reinterpret_cast<const float4*>(alpha)[e];   // broadcast
        float w = (head == 0) ? a.x : (head == 1) ? a.y : (head == 2) ? a.z : a.w;
        const __half2* ph =
            reinterpret_cast<const __half2*>(projh + (size_t)sn * (4 * DH)) + 2 * t;
        float2 p0 = __half22float2(ph[0]);
        float2 p1 = __half22float2(ph[1]);
        acc.x = fmaf(w, p0.x, acc.x);
        acc.y = fmaf(w, p0.y, acc.y);
        acc.z = fmaf(w, p1.x, acc.z);
        acc.w = fmaf(w, p1.y, acc.w);
    }
    float4 b = reinterpret_cast<const float4*>(bias)[t];
    acc.x = fmaf(acc.x, inv, b.x);
    acc.y = fmaf(acc.y, inv, b.y);
    acc.z = fmaf(acc.z, inv, b.z);
    acc.w = fmaf(acc.w, inv, b.w);
    if (ACT) {
        acc.x = lrelu(acc.x); acc.y = lrelu(acc.y);
        acc.z = lrelu(acc.z); acc.w = lrelu(acc.w);
    }
    if (OUT_HALF) {
        __half2* o = reinterpret_cast<__half2*>((__half*)outp + (size_t)d * (4 * DH)) + 2 * t;
        o[0] = __floats2half2_rn(acc.x, acc.y);
        o[1] = __floats2half2_rn(acc.z, acc.w);
    } else {
        reinterpret_cast<float4*>((float*)outp)[(size_t)d * C4 + t] = acc;
    }
}

// ---------------- launch ----------------
extern "C" void kernel_launch(void* const* d_in, const int* in_sizes, int n_in,
                              void* d_out, int out_size) {
    const float* x   = (const float*)d_in[0];
    const float* W1  = (const float*)d_in[1];
    const float* al1 = (const float*)d_in[2];
    const float* ar1 = (const float*)d_in[3];
    const float* b1  = (const float*)d_in[4];
    const float* W2  = (const float*)d_in[5];
    const float* al2 = (const float*)d_in[6];
    const float* ar2 = (const float*)d_in[7];
    const float* b2  = (const float*)d_in[8];
    const int*   src = (const int*)d_in[9];
    const int*   dst = (const int*)d_in[10];
    float* out = (float*)d_out;

    float *el1, *er1, *el2, *er2, *alpha, *invp, *degp, *wl2;
    __half *projh1, *projh2, *xh, *b1h, *w2h, *h1h;
    cudaGetSymbolAddress((void**)&projh1, g_projh1);
    cudaGetSymbolAddress((void**)&projh2, g_projh2);
    cudaGetSymbolAddress((void**)&xh, g_xh);
    cudaGetSymbolAddress((void**)&b1h, g_b1h);
    cudaGetSymbolAddress((void**)&w2h, g_w2h);
    cudaGetSymbolAddress((void**)&h1h, g_h1h);
    cudaGetSymbolAddress((void**)&wl2, g_wl2);
    cudaGetSymbolAddress((void**)&el1, g_el1);
    cudaGetSymbolAddress((void**)&er1, g_er1);
    cudaGetSymbolAddress((void**)&el2, g_el2);
    cudaGetSymbolAddress((void**)&er2, g_er2);
    cudaGetSymbolAddress((void**)&alpha, g_alpha);
    cudaGetSymbolAddress((void**)&invp, g_inv);
    cudaGetSymbolAddress((void**)&degp, g_deg);

    constexpr int SMEM64  = 3 * (GBM * LDA + GBK * (64 + 8)) * 2;    // 44544
    constexpr int SMEM128 = 3 * (GBM * LDA + GBK * (128 + 8)) * 2;   // 56832
    cudaFuncSetAttribute(gemm_f16<64, true>,   cudaFuncAttributeMaxDynamicSharedMemorySize, SMEM64);
    cudaFuncSetAttribute(gemm_f16<128, false>, cudaFuncAttributeMaxDynamicSharedMemorySize, SMEM128);

    cudaMemsetAsync(degp, 0, NN * sizeof(int));
    setup_kernel<<<(SETUP_TOTAL + 255) / 256, 256>>>(x, W1, al1, ar1, W2, al2, ar2, dst);
    scan_kernel<<<1, 1024>>>();
    scatter_kernel<<<(NE + 255) / 256, 256>>>(src, dst);

    const int ABLK = (NN + 7) / 8;
    const int GR = (NN + GBM - 1) / GBM;

    // layer 1: GEMM with appended score columns (scores1 fused, free)
    {
        dim3 grid((N1B + 63) / 64, GR);
        gemm_f16<64, true><<<grid, 256, SMEM64>>>(xh, b1h, projh1, el1, er1,
                                                  NN, 400, N1B, 300, XLD);
    }
    alpha_kernel<<<ABLK, 256>>>(el1, er1, alpha, invp);
    aggregate_kernel<100, true, true><<<NN, 128>>>(projh1, alpha, invp, b1, h1h);

    // layer 2: standalone scores2 (lean aggregate preserved)
    scores_w_kernel<400, __half><<<ABLK, 256>>>(h1h, 400, wl2, el2, er2);
    {
        dim3 grid(512 / 128, GR);
        gemm_f16<128, false><<<grid, 256, SMEM128>>>(h1h, w2h, projh2, nullptr, nullptr,
                                                     NN, 512, 512, 400, 400);
    }
    alpha_kernel<<<ABLK, 256>>>(el2, er2, alpha, invp);
    aggregate_kernel<128, false, false><<<NN, 128>>>(projh2, alpha, invp, b2, out);
}